// round 1
// baseline (speedup 1.0000x reference)
#include <cuda_runtime.h>
#include <math.h>

// Problem constants (fixed shapes)
#define BATCH 8
#define CDIM 512
#define HW 4096
#define NGRP 32
#define CPG 16          // CDIM / NGRP
#define EPSV 1e-6f

// ---------------- scratch (device globals: allocation-free) ----------------
__device__ float g_qn[(size_t)BATCH * CDIM * HW];
__device__ float g_vn[(size_t)BATCH * CDIM * HW];
__device__ float g_qp[(size_t)BATCH * CDIM * HW];
__device__ float g_kp[(size_t)BATCH * CDIM * HW];
__device__ float g_vp[(size_t)BATCH * CDIM * HW];
__device__ float g_ao[(size_t)BATCH * CDIM * HW];
__device__ float g_sc[(size_t)BATCH * HW * HW];   // 512 MiB scores/attn

// ---------------- GroupNorm: one block per (group, batch) ----------------
__global__ void gn_kernel(const float* __restrict__ x, float* __restrict__ y,
                          const float* __restrict__ gamma,
                          const float* __restrict__ beta) {
    const int grp = blockIdx.x;        // 0..31
    const int b   = blockIdx.y;        // 0..7
    const size_t base = ((size_t)b * CDIM + (size_t)grp * CPG) * HW;
    const int n4 = (CPG * HW) / 4;     // 16384 float4s
    const int tid = threadIdx.x;       // 256 threads

    const float4* x4 = (const float4*)(x + base);
    float s = 0.f, ss = 0.f;
    for (int i = tid; i < n4; i += 256) {
        float4 v = x4[i];
        s  += v.x + v.y + v.z + v.w;
        ss += v.x * v.x + v.y * v.y + v.z * v.z + v.w * v.w;
    }
    __shared__ float sh_s[256], sh_q[256];
    sh_s[tid] = s; sh_q[tid] = ss;
    __syncthreads();
    for (int off = 128; off > 0; off >>= 1) {
        if (tid < off) { sh_s[tid] += sh_s[tid + off]; sh_q[tid] += sh_q[tid + off]; }
        __syncthreads();
    }
    const float inv_n = 1.f / (float)(CPG * HW);
    const float mu   = sh_s[0] * inv_n;
    const float var  = sh_q[0] * inv_n - mu * mu;
    const float rstd = rsqrtf(var + EPSV);

    float4* y4 = (float4*)(y + base);
    for (int i = tid; i < n4; i += 256) {
        const int ch = grp * CPG + (i >> 10);     // 1024 float4s per channel
        const float a  = gamma[ch] * rstd;
        const float bb = beta[ch] - mu * a;
        float4 v = x4[i];
        float4 o;
        o.x = v.x * a + bb; o.y = v.y * a + bb;
        o.z = v.z * a + bb; o.w = v.w * a + bb;
        y4[i] = o;
    }
}

// ---------------- 128x128x8 SGEMM ----------------
// C[m][n] = sum_k A(k,m)*B[k][n], A(k,m) = TRANS_A ? A[k*lda+m] : A[m*lda+k]
// epilogue: out = (acc*alpha + bias[m] + res[m*N+n]) * oscale
template <bool TRANS_A, bool HAS_BIAS, bool HAS_RES>
__global__ __launch_bounds__(256)
void sgemm(const float* __restrict__ A, const float* __restrict__ B,
           float* __restrict__ C,
           const float* __restrict__ bias, const float* __restrict__ res,
           int M, int N, int K, int lda, int ldb,
           size_t sA, size_t sB, size_t sC, size_t sR,
           float alpha, float oscale) {
    const int bz = blockIdx.z;
    A += sA * bz; B += sB * bz; C += sC * bz;
    if (HAS_RES) res += sR * bz;

    const int m0 = blockIdx.y * 128;
    const int n0 = blockIdx.x * 128;

    __shared__ float As[8][128];
    __shared__ float Bs[8][128];

    const int tid = threadIdx.x;
    const int tx = tid & 15;           // 0..15
    const int ty = tid >> 4;           // 0..15

    float acc[8][8];
#pragma unroll
    for (int i = 0; i < 8; i++)
#pragma unroll
        for (int j = 0; j < 8; j++) acc[i][j] = 0.f;

    const int brow = tid >> 5;            // 0..7
    const int bcol = (tid & 31) << 2;     // 0..124
    const int ar = tid >> 1;              // 0..127  (NN A-load)
    const int ak = (tid & 1) << 2;        // 0 or 4

    for (int k0 = 0; k0 < K; k0 += 8) {
        // B tile: [8 x 128], n contiguous
        float4 bv = *(const float4*)&B[(size_t)(k0 + brow) * ldb + n0 + bcol];
        *(float4*)&Bs[brow][bcol] = bv;
        if (TRANS_A) {
            float4 av = *(const float4*)&A[(size_t)(k0 + brow) * lda + m0 + bcol];
            *(float4*)&As[brow][bcol] = av;
        } else {
            float4 av = *(const float4*)&A[(size_t)(m0 + ar) * lda + k0 + ak];
            As[ak + 0][ar] = av.x;
            As[ak + 1][ar] = av.y;
            As[ak + 2][ar] = av.z;
            As[ak + 3][ar] = av.w;
        }
        __syncthreads();
#pragma unroll
        for (int k = 0; k < 8; k++) {
            float4 a0 = *(float4*)&As[k][ty * 4];
            float4 a1 = *(float4*)&As[k][64 + ty * 4];
            float4 b0 = *(float4*)&Bs[k][tx * 4];
            float4 b1 = *(float4*)&Bs[k][64 + tx * 4];
            float am[8] = {a0.x, a0.y, a0.z, a0.w, a1.x, a1.y, a1.z, a1.w};
            float bn[8] = {b0.x, b0.y, b0.z, b0.w, b1.x, b1.y, b1.z, b1.w};
#pragma unroll
            for (int i = 0; i < 8; i++)
#pragma unroll
                for (int j = 0; j < 8; j++)
                    acc[i][j] += am[i] * bn[j];
        }
        __syncthreads();
    }

    // epilogue
#pragma unroll
    for (int i = 0; i < 8; i++) {
        const int m = m0 + ((i < 4) ? (ty * 4 + i) : (64 + ty * 4 + i - 4));
        const float bi = HAS_BIAS ? bias[m] : 0.f;
#pragma unroll
        for (int jj = 0; jj < 2; jj++) {
            const int n = n0 + ((jj == 0) ? (tx * 4) : (64 + tx * 4));
            float4 o;
            o.x = acc[i][jj * 4 + 0] * alpha + bi;
            o.y = acc[i][jj * 4 + 1] * alpha + bi;
            o.z = acc[i][jj * 4 + 2] * alpha + bi;
            o.w = acc[i][jj * 4 + 3] * alpha + bi;
            if (HAS_RES) {
                float4 r = *(const float4*)&res[(size_t)m * N + n];
                o.x += r.x; o.y += r.y; o.z += r.z; o.w += r.w;
            }
            o.x *= oscale; o.y *= oscale; o.z *= oscale; o.w *= oscale;
            *(float4*)&C[(size_t)m * N + n] = o;
        }
    }
}

// ---------------- softmax over x (dim -2) of S[b][x][y], in place ----------------
__global__ void softmax_kernel(float* __restrict__ S) {
    const int y = blockIdx.x * 256 + threadIdx.x;
    const size_t base = (size_t)blockIdx.y * HW * HW + y;

    float m = -1e30f, s = 0.f;
    for (int x = 0; x < HW; x += 16) {
        float v[16];
#pragma unroll
        for (int i = 0; i < 16; i++) v[i] = S[base + (size_t)(x + i) * HW];
#pragma unroll
        for (int i = 0; i < 16; i++) {
            float nm = fmaxf(m, v[i]);
            s = s * __expf(m - nm) + __expf(v[i] - nm);
            m = nm;
        }
    }
    const float inv = 1.f / s;
    for (int x = 0; x < HW; x += 16) {
        float v[16];
#pragma unroll
        for (int i = 0; i < 16; i++) v[i] = S[base + (size_t)(x + i) * HW];
#pragma unroll
        for (int i = 0; i < 16; i++)
            S[base + (size_t)(x + i) * HW] = __expf(v[i] - m) * inv;
    }
}

// ---------------- launch ----------------
extern "C" void kernel_launch(void* const* d_in, const int* in_sizes, int n_in,
                              void* d_out, int out_size) {
    const float* q     = (const float*)d_in[0];
    const float* gamma = (const float*)d_in[1];
    const float* beta  = (const float*)d_in[2];
    const float* wq    = (const float*)d_in[3];
    const float* bq    = (const float*)d_in[4];
    const float* wk    = (const float*)d_in[5];
    const float* bk    = (const float*)d_in[6];
    const float* wv    = (const float*)d_in[7];
    const float* bv    = (const float*)d_in[8];
    const float* wo    = (const float*)d_in[9];
    const float* bo    = (const float*)d_in[10];
    float* out = (float*)d_out;

    float *qn, *vn, *qp, *kp, *vp, *ao, *sc;
    cudaGetSymbolAddress((void**)&qn, g_qn);
    cudaGetSymbolAddress((void**)&vn, g_vn);
    cudaGetSymbolAddress((void**)&qp, g_qp);
    cudaGetSymbolAddress((void**)&kp, g_kp);
    cudaGetSymbolAddress((void**)&vp, g_vp);
    cudaGetSymbolAddress((void**)&ao, g_ao);
    cudaGetSymbolAddress((void**)&sc, g_sc);

    const size_t sX = (size_t)CDIM * HW;    // per-batch activation stride
    const size_t sS = (size_t)HW * HW;      // per-batch scores stride

    // 1,2: double GroupNorm
    dim3 gnGrid(NGRP, BATCH);
    gn_kernel<<<gnGrid, 256>>>(q, qn, gamma, beta);
    gn_kernel<<<gnGrid, 256>>>(qn, vn, gamma, beta);

    // 3-5: conv1x1 projections (W [C,C] x X [C,HW])
    dim3 convGrid(HW / 128, CDIM / 128, BATCH);
    sgemm<false, true, false><<<convGrid, 256>>>(wq, qn, qp, bq, nullptr,
        CDIM, HW, CDIM, CDIM, HW, 0, sX, sX, 0, 1.f, 1.f);
    sgemm<false, true, false><<<convGrid, 256>>>(wk, vn, kp, bk, nullptr,
        CDIM, HW, CDIM, CDIM, HW, 0, sX, sX, 0, 1.f, 1.f);
    sgemm<false, true, false><<<convGrid, 256>>>(wv, vn, vp, bv, nullptr,
        CDIM, HW, CDIM, CDIM, HW, 0, sX, sX, 0, 1.f, 1.f);

    // 6: scores[b,x,y] = scale * sum_c kp[b,c,x] * qp[b,c,y]   (TN)
    const float scale = 1.0f / sqrtf((float)CDIM);
    dim3 scGrid(HW / 128, HW / 128, BATCH);
    sgemm<true, false, false><<<scGrid, 256>>>(kp, qp, sc, nullptr, nullptr,
        HW, HW, CDIM, HW, HW, sX, sX, sS, 0, scale, 1.f);

    // 7: softmax over x (in place)
    softmax_kernel<<<dim3(HW / 256, BATCH), 256>>>(sc);

    // 8: ao[b,c,y] = sum_x vp[b,c,x] * attn[b,x,y]   (NN)
    sgemm<false, false, false><<<convGrid, 256>>>(vp, sc, ao, nullptr, nullptr,
        CDIM, HW, HW, HW, HW, sX, sS, sX, 0, 1.f, 1.f);

    // 9: out = (wo x ao + bo + q) / sqrt(2)
    const float inv_sqrt2 = 0.70710678118654752440f;
    sgemm<false, true, true><<<convGrid, 256>>>(wo, ao, out, bo, q,
        CDIM, HW, CDIM, CDIM, HW, 0, sX, sX, sX, 1.f, inv_sqrt2);
}